// round 11
// baseline (speedup 1.0000x reference)
#include <cuda_runtime.h>

#define FFT_N 8192
#define NT 256
#define NWARP 8
#define ROWS_MAX 4096

__device__ float g_best[ROWS_MAX];
__device__ float g_kl[ROWS_MAX];
__device__ int   g_count = 0;

// W32^j = exp(-2*pi*i*j/32), j=0..15
__constant__ float TWRE[16] = {
    1.0f,           0.98078528f,   0.92387953f,   0.83146961f,
    0.70710678f,    0.55557023f,   0.38268343f,   0.19509032f,
    0.0f,          -0.19509032f,  -0.38268343f,  -0.55557023f,
   -0.70710678f,   -0.83146961f,  -0.92387953f,  -0.98078528f };
__constant__ float TWIM[16] = {
   -0.0f,          -0.19509032f,  -0.38268343f,  -0.55557023f,
   -0.70710678f,   -0.83146961f,  -0.92387953f,  -0.98078528f,
   -1.0f,          -0.98078528f,  -0.92387953f,  -0.83146961f,
   -0.70710678f,   -0.55557023f,  -0.38268343f,  -0.19509032f };

#define SIDX(i)  ((i) + ((i) >> 4))
#define TSIDX(i) ((i) + ((i) >> 5))

union F2U { float2 f; unsigned long long u; };

__device__ __forceinline__ float2 cadd(float2 a, float2 b) {
    F2U x, y, r; x.f = a; y.f = b;
    asm("add.rn.f32x2 %0, %1, %2;" : "=l"(r.u) : "l"(x.u), "l"(y.u));
    return r.f;
}
__device__ __forceinline__ float2 csub(float2 a, float2 b) {
    F2U x, y, r; x.f = a; y.f = b;
    asm("sub.rn.f32x2 %0, %1, %2;" : "=l"(r.u) : "l"(x.u), "l"(y.u));
    return r.f;
}
__device__ __forceinline__ float2 cfma2(float2 a, float2 b, float2 c) {
    F2U x, y, z, r; x.f = a; y.f = b; z.f = c;
    asm("fma.rn.f32x2 %0, %1, %2, %3;" : "=l"(r.u) : "l"(x.u), "l"(y.u), "l"(z.u));
    return r.f;
}
__device__ __forceinline__ float2 cmul(float2 a, float2 b) {
    return make_float2(fmaf(a.x, b.x, -a.y * b.y), fmaf(a.x, b.y, a.y * b.x));
}

__host__ __device__ constexpr int brevc(int x, int bits) {
    int r = 0;
    for (int i = 0; i < bits; i++) r |= ((x >> i) & 1) << (bits - 1 - i);
    return r;
}

template <int LOGM>
__device__ __forceinline__ void dif_fft(float2* a) {
    constexpr int M = 1 << LOGM;
#pragma unroll
    for (int s = 0; s < LOGM; s++) {
        const int half = M >> (s + 1);
#pragma unroll
        for (int b = 0; b < (M / 2) / half; b++) {
#pragma unroll
            for (int j = 0; j < half; j++) {
                const int i0 = b * 2 * half + j;
                const int i1 = i0 + half;
                const float2 u = a[i0], v = a[i1];
                a[i0] = cadd(u, v);
                const float2 d = csub(u, v);
                const int tw = (j << s) * (32 / M);
                if (tw == 0) {
                    a[i1] = d;
                } else if (tw == 8) {                      // * (-i)
                    a[i1] = make_float2(d.y, -d.x);
                } else {
                    const float c = TWRE[tw], ss = TWIM[tw];
                    a[i1] = make_float2(fmaf(d.x, c, -d.y * ss), fmaf(d.x, ss, d.y * c));
                }
            }
        }
    }
}

__device__ __forceinline__ float4 blockReduceSum4(float4 v) {
    __shared__ float4 scr[NWARP];
#pragma unroll
    for (int o = 16; o; o >>= 1) {
        v.x += __shfl_xor_sync(0xffffffffu, v.x, o);
        v.y += __shfl_xor_sync(0xffffffffu, v.y, o);
        v.z += __shfl_xor_sync(0xffffffffu, v.z, o);
        v.w += __shfl_xor_sync(0xffffffffu, v.w, o);
    }
    const int w = threadIdx.x >> 5, l = threadIdx.x & 31;
    if (l == 0) scr[w] = v;
    __syncthreads();
    if (w == 0) {
        v = (l < NWARP) ? scr[l] : make_float4(0.f, 0.f, 0.f, 0.f);
#pragma unroll
        for (int o = NWARP >> 1; o; o >>= 1) {
            v.x += __shfl_xor_sync(0xffffffffu, v.x, o);
            v.y += __shfl_xor_sync(0xffffffffu, v.y, o);
            v.z += __shfl_xor_sync(0xffffffffu, v.z, o);
            v.w += __shfl_xor_sync(0xffffffffu, v.w, o);
        }
        if (l == 0) scr[0] = v;
    }
    __syncthreads();
    float4 r = scr[0];
    __syncthreads();
    return r;
}

// slot of X[k] in S (phase-2b output layout)
__device__ __forceinline__ int xslot(int k) {
    return (k & 31) * 256 + ((k >> 5) & 15) * 16 + (k >> 9);
}

__global__ void __launch_bounds__(NT, 2)
row_kernel(const float* __restrict__ preds, const float* __restrict__ targets,
           float* __restrict__ out, int rows) {
    extern __shared__ float smraw[];
    float2* S  = (float2*)smraw;            // 8704 float2 (skewed)
    float*  ts = smraw + 2 * 8704;          // 8448 floats (skewed)
    __shared__ float wcov[NWARP * 31];
    __shared__ float sred[32];
    __shared__ int islast;

    const int row = blockIdx.x;
    const int tid = threadIdx.x;
    const float*  __restrict__ pr  = preds   + (size_t)row * FFT_N;
    const float*  __restrict__ tr  = targets + (size_t)row * FFT_N;
    const float4* __restrict__ pr4 = (const float4*)pr;

    // ===== Phase 1: strided load, packed stats, 32-pt register FFT, twiddle, store
    float2 a[32];
    float2 s_pt  = make_float2(0.f, 0.f);
    float2 sq_pt = make_float2(0.f, 0.f);
#pragma unroll
    for (int n1 = 0; n1 < 32; n1++) {
        const int idx = (n1 << 8) + tid;
        const float p = pr[idx];
        const float t = tr[idx];
        a[n1] = make_float2(p, t);
        ts[TSIDX(idx)] = t;
        s_pt  = cadd(s_pt, a[n1]);
        sq_pt = cfma2(a[n1], a[n1], sq_pt);
    }
    dif_fft<5>(a);
    {
        float s_, c_;
        __sincosf((-6.283185307179586f / FFT_N) * (float)tid, &s_, &c_);
        const float2 w1 = make_float2(c_, s_);
        const float2 w2 = cmul(w1, w1);
        const float2 w4 = cmul(w2, w2);
        S[SIDX(tid)] = a[0];
        {
            float2 c = w1;
#pragma unroll
            for (int k1 = 1; k1 < 32; k1 += 4) { S[SIDX(k1 * 256 + tid)] = cmul(a[brevc(k1, 5)], c); c = cmul(c, w4); }
        }
        {
            float2 c = w2;
#pragma unroll
            for (int k1 = 2; k1 < 32; k1 += 4) { S[SIDX(k1 * 256 + tid)] = cmul(a[brevc(k1, 5)], c); c = cmul(c, w4); }
        }
        {
            float2 c = cmul(w2, w1);
#pragma unroll
            for (int k1 = 3; k1 < 32; k1 += 4) { S[SIDX(k1 * 256 + tid)] = cmul(a[brevc(k1, 5)], c); c = cmul(c, w4); }
        }
        {
            float2 c = w4;
#pragma unroll
            for (int k1 = 4; k1 < 32; k1 += 4) { S[SIDX(k1 * 256 + tid)] = cmul(a[brevc(k1, 5)], c); c = cmul(c, w4); }
        }
    }
    const float4 red = blockReduceSum4(make_float4(s_pt.x, s_pt.y, sq_pt.x, sq_pt.y));
    const float invN = 1.0f / (float)FFT_N;
    const float sqp_c = red.z - red.x * red.x * invN;
    const float sqt_c = red.w - red.y * red.y * invN;
    const float inv_denom = rsqrtf((sqp_c + 1e-8f) * (sqt_c + 1e-8f));
    const float mean_corr = red.x * red.y * invN;

    // ===== Cross-correlation (register-blocked; ts from smem, preds via L1/L2)
    float cov[32];
#pragma unroll
    for (int s = 0; s < 32; s++) cov[s] = 0.0f;
#pragma unroll
    for (int q = 0; q < 2; q++) {
        const int base = tid * 32 + q * 16;
        float pk[16];
        const float4* pb = pr4 + (base >> 2);
#pragma unroll
        for (int n = 0; n < 4; n++) {
            float4 v = pb[n];
            pk[4 * n + 0] = v.x; pk[4 * n + 1] = v.y;
            pk[4 * n + 2] = v.z; pk[4 * n + 3] = v.w;
        }
        float twin[46];
#pragma unroll
        for (int m = 0; m < 46; m++) {
            const int idx = (base - 15 + m) & (FFT_N - 1);
            twin[m] = ts[TSIDX(idx)];
        }
#pragma unroll
        for (int k = 0; k < 16; k++)
#pragma unroll
            for (int s = 0; s < 31; s++)
                cov[s] = fmaf(pk[k], twin[k + s], cov[s]);
    }
    // Butterfly multi-value warp reduction: lane s ends with warp-total of cov[s]
    {
        const int lane = tid & 31;
#pragma unroll
        for (int o = 16; o; o >>= 1) {
            const bool up = (lane & o) != 0;
#pragma unroll
            for (int i = 0; i < o; i++) {
                const float send = up ? cov[i] : cov[i + o];
                const float recv = __shfl_xor_sync(0xffffffffu, send, o);
                cov[i] = (up ? cov[i + o] : cov[i]) + recv;
            }
        }
        if (lane < 31) wcov[(tid >> 5) * 31 + lane] = cov[0];
    }
    // (no sync yet — post-phase-2a barrier covers wcov visibility)

    // ===== Phase 2a: 16-pt FFT over m1 for each (k1, m2); in-place per-thread
    {
        const int m2 = tid & 15;
        float sm_, cm_;
        __sincosf((-6.283185307179586f / 256.0f) * (float)m2, &sm_, &cm_);
        const float2 wm1 = make_float2(cm_, sm_);
        const float2 wm2 = cmul(wm1, wm1);
        const float2 wm4 = cmul(wm2, wm2);
#pragma unroll
        for (int pair = 0; pair < 2; pair++) {
            const int p  = tid + pair * 256;
            const int k1 = p >> 4;
            float2 b[16];
#pragma unroll
            for (int m1 = 0; m1 < 16; m1++)
                b[m1] = S[SIDX(k1 * 256 + m1 * 16 + m2)];
            dif_fft<4>(b);
            S[SIDX(k1 * 256 + 0 * 16 + m2)] = b[0];
            float2 cg[4];
            cg[1] = wm1; cg[2] = wm2; cg[3] = cmul(wm2, wm1);
#pragma unroll
            for (int g = 1; g < 4; g++) {
                float2 c = cg[g];
#pragma unroll
                for (int j1 = g; j1 < 16; j1 += 4) {
                    S[SIDX(k1 * 256 + j1 * 16 + m2)] = cmul(b[brevc(j1, 4)], c);
                    c = cmul(c, wm4);
                }
            }
            {
                float2 c = wm4;
#pragma unroll
                for (int j1 = 4; j1 < 16; j1 += 4) {
                    S[SIDX(k1 * 256 + j1 * 16 + m2)] = cmul(b[brevc(j1, 4)], c);
                    c = cmul(c, wm4);
                }
            }
        }
    }
    __syncthreads();   // covers phase-2a S writes AND wcov writes

    // ===== Pearson finalize on warp 0 (concurrent with phase 2b on other warps)
    if (tid < 32) {
        if (tid < 31) {
            float v = 0.0f;
#pragma unroll
            for (int w = 0; w < NWARP; w++) v += wcov[w * 31 + tid];
            sred[tid] = (v - mean_corr) * inv_denom;
        }
        __syncwarp();
        if (tid == 0) {
            float best = -1.0f;
#pragma unroll
            for (int s = 0; s < 31; s++) best = fmaxf(best, sred[s]);
            g_best[row] = best;
        }
    }

    // ===== Phase 2b: 16-pt FFT over m2 for each (k1, j1); in-place per-thread
#pragma unroll
    for (int pair = 0; pair < 2; pair++) {
        const int p  = tid + pair * 256;
        const int k1 = p >> 4;
        const int j1 = p & 15;
        float2 c[16];
#pragma unroll
        for (int m2 = 0; m2 < 16; m2++)
            c[m2] = S[SIDX(k1 * 256 + j1 * 16 + m2)];
        dif_fft<4>(c);
#pragma unroll
        for (int j2 = 0; j2 < 16; j2++)
            S[SIDX(k1 * 256 + j1 * 16 + j2)] = c[brevc(j2, 4)];
    }
    __syncthreads();

    // ===== Parseval: power sums from stats + Nyquist bin (xslot(4096)=8, SIDX(8)=8)
    const float2 znyq = S[8];
    const float Sp = 0.5f * fmaf((float)FFT_N, sqp_c, znyq.x * znyq.x);
    const float St = 0.5f * fmaf((float)FFT_N, sqt_c, znyq.y * znyq.y);
    const float invSp = 1.0f / (Sp + 1e-8f);
    const float invSt = 1.0f / (St + 1e-8f);

    // ===== Single untangle + KL pass over bins 1..N/2 (single-log form)
    float kl = 0.0f;
#pragma unroll
    for (int cbin = 0; cbin < 16; cbin++) {
        const int k = tid * 16 + cbin + 1;
        const float2 za = S[SIDX(xslot(k))];
        const float2 zb = S[SIDX(xslot(FFT_N - k))];
        const float2 s1 = cadd(za, zb);   // (prx, pty)
        const float2 s2 = csub(za, zb);   // (ptx, pry)
        const float Pp = 0.25f * fmaf(s1.x, s1.x, s2.y * s2.y);
        const float Pt = 0.25f * fmaf(s2.x, s2.x, s1.y * s1.y);
        const float qp = Pp * invSp;
        const float qt = Pt * invSt;
        kl = fmaf(qt, __logf(__fdividef(qt + 1e-8f, qp + 1e-8f)), kl);
    }
    const float4 r3 = blockReduceSum4(make_float4(kl, 0.f, 0.f, 0.f));
    if (tid == 0) g_kl[row] = r3.x;

    // ===== Last-arriving block performs the deterministic final mean
    __threadfence();
    if (tid == 0) {
        const int old = atomicAdd(&g_count, 1);
        islast = (old == (int)gridDim.x - 1);
    }
    __syncthreads();
    if (islast) {
        float b = 0.0f, k = 0.0f;
        for (int i = tid; i < rows; i += NT) {
            b += g_best[i];
            k += g_kl[i];
        }
        const float4 r = blockReduceSum4(make_float4(b, k, 0.f, 0.f));
        if (tid == 0) {
            const float inv_rows = 1.0f / (float)rows;
            out[0] = 0.5f * (1.0f - r.x * inv_rows) + 0.5f * (r.y * inv_rows);
            g_count = 0;   // reset for next graph replay
        }
    }
}

extern "C" void kernel_launch(void* const* d_in, const int* in_sizes, int n_in,
                              void* d_out, int out_size) {
    const float* preds   = (const float*)d_in[0];
    const float* targets = (const float*)d_in[1];
    const int rows = in_sizes[0] / FFT_N;

    const size_t smem = (size_t)8704 * sizeof(float2) + (size_t)8448 * sizeof(float);  // 103424 B
    cudaFuncSetAttribute(row_kernel, cudaFuncAttributeMaxDynamicSharedMemorySize, (int)smem);

    row_kernel<<<rows, NT, smem>>>(preds, targets, (float*)d_out, rows);
}

// round 12
// speedup vs baseline: 1.0182x; 1.0182x over previous
#include <cuda_runtime.h>

#define FFT_N 8192
#define NT 256
#define NWARP 8
#define ROWS_MAX 4096

__device__ float g_best[ROWS_MAX];
__device__ float g_kl[ROWS_MAX];
__device__ int   g_count = 0;

// W32^j = exp(-2*pi*i*j/32), j=0..15
__constant__ float TWRE[16] = {
    1.0f,           0.98078528f,   0.92387953f,   0.83146961f,
    0.70710678f,    0.55557023f,   0.38268343f,   0.19509032f,
    0.0f,          -0.19509032f,  -0.38268343f,  -0.55557023f,
   -0.70710678f,   -0.83146961f,  -0.92387953f,  -0.98078528f };
__constant__ float TWIM[16] = {
   -0.0f,          -0.19509032f,  -0.38268343f,  -0.55557023f,
   -0.70710678f,   -0.83146961f,  -0.92387953f,  -0.98078528f,
   -1.0f,          -0.98078528f,  -0.92387953f,  -0.83146961f,
   -0.70710678f,   -0.55557023f,  -0.38268343f,  -0.19509032f };

#define SIDX(i)  ((i) + ((i) >> 4))
#define TSIDX(i) ((i) + ((i) >> 5))

union F2U { float2 f; unsigned long long u; };

__device__ __forceinline__ float2 cadd(float2 a, float2 b) {
    F2U x, y, r; x.f = a; y.f = b;
    asm("add.rn.f32x2 %0, %1, %2;" : "=l"(r.u) : "l"(x.u), "l"(y.u));
    return r.f;
}
__device__ __forceinline__ float2 csub(float2 a, float2 b) {
    F2U x, y, r; x.f = a; y.f = b;
    asm("sub.rn.f32x2 %0, %1, %2;" : "=l"(r.u) : "l"(x.u), "l"(y.u));
    return r.f;
}
__device__ __forceinline__ float2 cfma2(float2 a, float2 b, float2 c) {
    F2U x, y, z, r; x.f = a; y.f = b; z.f = c;
    asm("fma.rn.f32x2 %0, %1, %2, %3;" : "=l"(r.u) : "l"(x.u), "l"(y.u), "l"(z.u));
    return r.f;
}
__device__ __forceinline__ float2 cmul(float2 a, float2 b) {
    return make_float2(fmaf(a.x, b.x, -a.y * b.y), fmaf(a.x, b.y, a.y * b.x));
}

__host__ __device__ constexpr int brevc(int x, int bits) {
    int r = 0;
    for (int i = 0; i < bits; i++) r |= ((x >> i) & 1) << (bits - 1 - i);
    return r;
}

template <int LOGM>
__device__ __forceinline__ void dif_fft(float2* a) {
    constexpr int M = 1 << LOGM;
#pragma unroll
    for (int s = 0; s < LOGM; s++) {
        const int half = M >> (s + 1);
#pragma unroll
        for (int b = 0; b < (M / 2) / half; b++) {
#pragma unroll
            for (int j = 0; j < half; j++) {
                const int i0 = b * 2 * half + j;
                const int i1 = i0 + half;
                const float2 u = a[i0], v = a[i1];
                a[i0] = cadd(u, v);
                const float2 d = csub(u, v);
                const int tw = (j << s) * (32 / M);
                if (tw == 0) {
                    a[i1] = d;
                } else if (tw == 8) {                      // * (-i)
                    a[i1] = make_float2(d.y, -d.x);
                } else {
                    const float c = TWRE[tw], ss = TWIM[tw];
                    a[i1] = make_float2(fmaf(d.x, c, -d.y * ss), fmaf(d.x, ss, d.y * c));
                }
            }
        }
    }
}

__device__ __forceinline__ float4 blockReduceSum4(float4 v) {
    __shared__ float4 scr[NWARP];
#pragma unroll
    for (int o = 16; o; o >>= 1) {
        v.x += __shfl_xor_sync(0xffffffffu, v.x, o);
        v.y += __shfl_xor_sync(0xffffffffu, v.y, o);
        v.z += __shfl_xor_sync(0xffffffffu, v.z, o);
        v.w += __shfl_xor_sync(0xffffffffu, v.w, o);
    }
    const int w = threadIdx.x >> 5, l = threadIdx.x & 31;
    if (l == 0) scr[w] = v;
    __syncthreads();
    if (w == 0) {
        v = (l < NWARP) ? scr[l] : make_float4(0.f, 0.f, 0.f, 0.f);
#pragma unroll
        for (int o = NWARP >> 1; o; o >>= 1) {
            v.x += __shfl_xor_sync(0xffffffffu, v.x, o);
            v.y += __shfl_xor_sync(0xffffffffu, v.y, o);
            v.z += __shfl_xor_sync(0xffffffffu, v.z, o);
            v.w += __shfl_xor_sync(0xffffffffu, v.w, o);
        }
        if (l == 0) scr[0] = v;
    }
    __syncthreads();
    float4 r = scr[0];
    __syncthreads();
    return r;
}

// slot of X[k] in S (phase-2b output layout)
__device__ __forceinline__ int xslot(int k) {
    return (k & 31) * 256 + ((k >> 5) & 15) * 16 + (k >> 9);
}

__global__ void __launch_bounds__(NT, 2)
row_kernel(const float* __restrict__ preds, const float* __restrict__ targets,
           float* __restrict__ out, int rows) {
    extern __shared__ float smraw[];
    float2* S  = (float2*)smraw;            // 8704 float2 (skewed)
    float*  ts = smraw + 2 * 8704;          // 8448 floats (skewed)
    __shared__ float wcov[NWARP * 31];
    __shared__ float sred[32];
    __shared__ int islast;

    const int row = blockIdx.x;
    const int tid = threadIdx.x;
    const float*  __restrict__ pr  = preds   + (size_t)row * FFT_N;
    const float*  __restrict__ tr  = targets + (size_t)row * FFT_N;
    const float4* __restrict__ pr4 = (const float4*)pr;

    // ===== Phase 1: strided load, packed stats, 32-pt register FFT, twiddle, store
    float2 a[32];
    float2 s_pt  = make_float2(0.f, 0.f);
    float2 sq_pt = make_float2(0.f, 0.f);
#pragma unroll
    for (int n1 = 0; n1 < 32; n1++) {
        const int idx = (n1 << 8) + tid;
        const float p = pr[idx];
        const float t = tr[idx];
        a[n1] = make_float2(p, t);
        ts[TSIDX(idx)] = t;
        s_pt  = cadd(s_pt, a[n1]);
        sq_pt = cfma2(a[n1], a[n1], sq_pt);
    }
    dif_fft<5>(a);
    {
        float s_, c_;
        __sincosf((-6.283185307179586f / FFT_N) * (float)tid, &s_, &c_);
        const float2 w1 = make_float2(c_, s_);
        const float2 w2 = cmul(w1, w1);
        const float2 w4 = cmul(w2, w2);
        S[SIDX(tid)] = a[0];
        {
            float2 c = w1;
#pragma unroll
            for (int k1 = 1; k1 < 32; k1 += 4) { S[SIDX(k1 * 256 + tid)] = cmul(a[brevc(k1, 5)], c); c = cmul(c, w4); }
        }
        {
            float2 c = w2;
#pragma unroll
            for (int k1 = 2; k1 < 32; k1 += 4) { S[SIDX(k1 * 256 + tid)] = cmul(a[brevc(k1, 5)], c); c = cmul(c, w4); }
        }
        {
            float2 c = cmul(w2, w1);
#pragma unroll
            for (int k1 = 3; k1 < 32; k1 += 4) { S[SIDX(k1 * 256 + tid)] = cmul(a[brevc(k1, 5)], c); c = cmul(c, w4); }
        }
        {
            float2 c = w4;
#pragma unroll
            for (int k1 = 4; k1 < 32; k1 += 4) { S[SIDX(k1 * 256 + tid)] = cmul(a[brevc(k1, 5)], c); c = cmul(c, w4); }
        }
    }
    const float4 red = blockReduceSum4(make_float4(s_pt.x, s_pt.y, sq_pt.x, sq_pt.y));
    const float invN = 1.0f / (float)FFT_N;
    const float sqp_c = red.z - red.x * red.x * invN;
    const float sqt_c = red.w - red.y * red.y * invN;
    const float inv_denom = rsqrtf((sqp_c + 1e-8f) * (sqt_c + 1e-8f));
    const float mean_corr = red.x * red.y * invN;

    // ===== Cross-correlation (register-blocked; ts from smem, preds via L1/L2)
    float cov[32];
#pragma unroll
    for (int s = 0; s < 32; s++) cov[s] = 0.0f;
#pragma unroll
    for (int q = 0; q < 2; q++) {
        const int base = tid * 32 + q * 16;
        float pk[16];
        const float4* pb = pr4 + (base >> 2);
#pragma unroll
        for (int n = 0; n < 4; n++) {
            float4 v = pb[n];
            pk[4 * n + 0] = v.x; pk[4 * n + 1] = v.y;
            pk[4 * n + 2] = v.z; pk[4 * n + 3] = v.w;
        }
        float twin[46];
#pragma unroll
        for (int m = 0; m < 46; m++) {
            const int idx = (base - 15 + m) & (FFT_N - 1);
            twin[m] = ts[TSIDX(idx)];
        }
#pragma unroll
        for (int k = 0; k < 16; k++)
#pragma unroll
            for (int s = 0; s < 31; s++)
                cov[s] = fmaf(pk[k], twin[k + s], cov[s]);
    }
    // Butterfly multi-value warp reduction: lane s ends with warp-total of cov[s]
    {
        const int lane = tid & 31;
#pragma unroll
        for (int o = 16; o; o >>= 1) {
            const bool up = (lane & o) != 0;
#pragma unroll
            for (int i = 0; i < o; i++) {
                const float send = up ? cov[i] : cov[i + o];
                const float recv = __shfl_xor_sync(0xffffffffu, send, o);
                cov[i] = (up ? cov[i + o] : cov[i]) + recv;
            }
        }
        if (lane < 31) wcov[(tid >> 5) * 31 + lane] = cov[0];
    }
    // (no sync yet — post-phase-2a barrier covers wcov visibility)

    // ===== Phase 2a: 16-pt FFT over m1 for each (k1, m2); in-place per-thread
    {
        const int m2 = tid & 15;
        float sm_, cm_;
        __sincosf((-6.283185307179586f / 256.0f) * (float)m2, &sm_, &cm_);
        const float2 wm1 = make_float2(cm_, sm_);
        const float2 wm2 = cmul(wm1, wm1);
        const float2 wm4 = cmul(wm2, wm2);
#pragma unroll
        for (int pair = 0; pair < 2; pair++) {
            const int p  = tid + pair * 256;
            const int k1 = p >> 4;
            float2 b[16];
#pragma unroll
            for (int m1 = 0; m1 < 16; m1++)
                b[m1] = S[SIDX(k1 * 256 + m1 * 16 + m2)];
            dif_fft<4>(b);
            S[SIDX(k1 * 256 + 0 * 16 + m2)] = b[0];
            float2 cg[4];
            cg[1] = wm1; cg[2] = wm2; cg[3] = cmul(wm2, wm1);
#pragma unroll
            for (int g = 1; g < 4; g++) {
                float2 c = cg[g];
#pragma unroll
                for (int j1 = g; j1 < 16; j1 += 4) {
                    S[SIDX(k1 * 256 + j1 * 16 + m2)] = cmul(b[brevc(j1, 4)], c);
                    c = cmul(c, wm4);
                }
            }
            {
                float2 c = wm4;
#pragma unroll
                for (int j1 = 4; j1 < 16; j1 += 4) {
                    S[SIDX(k1 * 256 + j1 * 16 + m2)] = cmul(b[brevc(j1, 4)], c);
                    c = cmul(c, wm4);
                }
            }
        }
    }
    __syncthreads();   // covers phase-2a S writes AND wcov writes

    // ===== Pearson finalize on warp 0 (concurrent with phase 2b on other warps)
    if (tid < 32) {
        if (tid < 31) {
            float v = 0.0f;
#pragma unroll
            for (int w = 0; w < NWARP; w++) v += wcov[w * 31 + tid];
            sred[tid] = (v - mean_corr) * inv_denom;
        }
        __syncwarp();
        if (tid == 0) {
            float best = -1.0f;
#pragma unroll
            for (int s = 0; s < 31; s++) best = fmaxf(best, sred[s]);
            g_best[row] = best;
        }
    }

    // ===== Phase 2b: 16-pt FFT over m2 for each (k1, j1); in-place per-thread
#pragma unroll
    for (int pair = 0; pair < 2; pair++) {
        const int p  = tid + pair * 256;
        const int k1 = p >> 4;
        const int j1 = p & 15;
        float2 c[16];
#pragma unroll
        for (int m2 = 0; m2 < 16; m2++)
            c[m2] = S[SIDX(k1 * 256 + j1 * 16 + m2)];
        dif_fft<4>(c);
#pragma unroll
        for (int j2 = 0; j2 < 16; j2++)
            S[SIDX(k1 * 256 + j1 * 16 + j2)] = c[brevc(j2, 4)];
    }
    __syncthreads();

    // ===== Parseval: power sums from stats + Nyquist bin (xslot(4096)=8, SIDX(8)=8)
    const float2 znyq = S[8];
    const float Sp = 0.5f * fmaf((float)FFT_N, sqp_c, znyq.x * znyq.x);
    const float St = 0.5f * fmaf((float)FFT_N, sqt_c, znyq.y * znyq.y);
    const float invSp = 1.0f / (Sp + 1e-8f);
    const float invSt = 1.0f / (St + 1e-8f);

    // ===== Single untangle + KL pass over bins 1..N/2 (single-log form)
    float kl = 0.0f;
#pragma unroll
    for (int cbin = 0; cbin < 16; cbin++) {
        const int k = tid * 16 + cbin + 1;
        const float2 za = S[SIDX(xslot(k))];
        const float2 zb = S[SIDX(xslot(FFT_N - k))];
        const float2 s1 = cadd(za, zb);   // (prx, pty)
        const float2 s2 = csub(za, zb);   // (ptx, pry)
        const float Pp = 0.25f * fmaf(s1.x, s1.x, s2.y * s2.y);
        const float Pt = 0.25f * fmaf(s2.x, s2.x, s1.y * s1.y);
        const float qp = Pp * invSp;
        const float qt = Pt * invSt;
        kl = fmaf(qt, __logf(__fdividef(qt + 1e-8f, qp + 1e-8f)), kl);
    }
    const float4 r3 = blockReduceSum4(make_float4(kl, 0.f, 0.f, 0.f));
    if (tid == 0) g_kl[row] = r3.x;

    // ===== Last-arriving block performs the deterministic final mean
    __threadfence();
    if (tid == 0) {
        const int old = atomicAdd(&g_count, 1);
        islast = (old == (int)gridDim.x - 1);
    }
    __syncthreads();
    if (islast) {
        float b = 0.0f, k = 0.0f;
        for (int i = tid; i < rows; i += NT) {
            b += g_best[i];
            k += g_kl[i];
        }
        const float4 r = blockReduceSum4(make_float4(b, k, 0.f, 0.f));
        if (tid == 0) {
            const float inv_rows = 1.0f / (float)rows;
            out[0] = 0.5f * (1.0f - r.x * inv_rows) + 0.5f * (r.y * inv_rows);
            g_count = 0;   // reset for next graph replay
        }
    }
}

extern "C" void kernel_launch(void* const* d_in, const int* in_sizes, int n_in,
                              void* d_out, int out_size) {
    const float* preds   = (const float*)d_in[0];
    const float* targets = (const float*)d_in[1];
    const int rows = in_sizes[0] / FFT_N;

    const size_t smem = (size_t)8704 * sizeof(float2) + (size_t)8448 * sizeof(float);  // 103424 B
    cudaFuncSetAttribute(row_kernel, cudaFuncAttributeMaxDynamicSharedMemorySize, (int)smem);

    row_kernel<<<rows, NT, smem>>>(preds, targets, (float*)d_out, rows);
}